// round 2
// baseline (speedup 1.0000x reference)
#include <cuda_runtime.h>
#include <cuda_bf16.h>
#include <math_constants.h>

// Problem constants
#define NUM_CODES   2560
#define DIM         128
#define N_TOKENS    65536          // 16 * 64 * 64
#define TOT_ELEMS   8388608        // 16 * 128 * 64 * 64
#define TOK_PER_BLK 64
#define CODES_PER_CHUNK 256
#define N_CHUNKS    (NUM_CODES / CODES_PER_CHUNK)   // 10
#define ZSTRIDE     132            // padded row stride (words); 132*4=528B = 33*16B aligned

// scratch (static device globals are the allowed scratch mechanism)
__device__ float  g_enorm[NUM_CODES];
__device__ double g_s1;   // sum (z_q - z)^2   (fp32-squared, accumulated in double)
__device__ double g_s3;   // sum (batch - out)^2

// ---------------- packed f32x2 helpers ----------------
__device__ __forceinline__ unsigned long long ffma2(unsigned long long a,
                                                    unsigned long long b,
                                                    unsigned long long c) {
    unsigned long long d;
    asm("fma.rn.f32x2 %0, %1, %2, %3;" : "=l"(d) : "l"(a), "l"(b), "l"(c));
    return d;
}
__device__ __forceinline__ void unpack2(unsigned long long p, float& lo, float& hi) {
    asm("mov.b64 {%0, %1}, %2;" : "=f"(lo), "=f"(hi) : "l"(p));
}

// ---------------- prep: enorm + zero loss accumulators ----------------
__global__ void vq_prep(const float* __restrict__ w) {
    if (blockIdx.x == 0 && threadIdx.x == 0) { g_s1 = 0.0; g_s3 = 0.0; }
    int gw   = (blockIdx.x * blockDim.x + threadIdx.x) >> 5;   // global warp id = code
    int lane = threadIdx.x & 31;
    if (gw < NUM_CODES) {
        const float* row = w + (size_t)gw * DIM;
        float s = 0.0f;
        #pragma unroll
        for (int k = lane; k < DIM; k += 32) {
            float v = row[k];
            s = __fadd_rn(s, __fmul_rn(v, v));
        }
        #pragma unroll
        for (int off = 16; off > 0; off >>= 1)
            s += __shfl_xor_sync(0xffffffffu, s, off);
        if (lane == 0) g_enorm[gw] = s;
    }
}

// ---------------- main kernel ----------------
// grid: N_TOKENS/64 = 1024 blocks, 256 threads
// smem layout (floats):
//   zs [64][132]      : 8448
//   ws [256][132]     : 33792   (reused for argmin reduction + double loss reduce)
//   zn [64], en[256], inds[64]
__global__ void __launch_bounds__(256, 1)
vq_main(const float* __restrict__ batch, const float* __restrict__ w,
        float* __restrict__ out) {
    extern __shared__ float sm[];
    float* zs   = sm;                          // 64*132
    float* ws   = sm + TOK_PER_BLK * ZSTRIDE;  // 256*132
    float* zn   = ws + CODES_PER_CHUNK * ZSTRIDE;  // 64
    float* en   = zn + TOK_PER_BLK;                // 256
    int*   inds = (int*)(en + CODES_PER_CHUNK);    // 64

    // reduction scratch aliases ws (only used after compute loop / between syncs)
    float* rv = ws;                   // [64][32]
    int*   ri = (int*)(ws + 2048);    // [64][32]

    const int tid = threadIdx.x;
    const int tg  = tid & 7;          // token group: tokens tg, tg+8, ..., tg+56
    const int cg  = tid >> 3;         // code group:  codes  cg, cg+32, ..., cg+224 (per chunk)

    const int n0  = blockIdx.x * TOK_PER_BLK;
    const int b   = n0 >> 12;                 // 4096 tokens per batch image
    const int hw0 = n0 & 4095;
    const float* zbase = batch + (size_t)b * (128 * 4096) + hw0;

    // ---- load z tile: zs[t][c], global reads coalesced along tokens ----
    for (int idx = tid; idx < TOK_PER_BLK * DIM; idx += 256) {
        int c = idx >> 6;
        int t = idx & 63;
        zs[t * ZSTRIDE + c] = zbase[(size_t)c * 4096 + t];
    }
    __syncthreads();

    // ---- znorm per token (plain mul+add to mirror sum-of-squares) ----
    if (tid < TOK_PER_BLK) {
        float s = 0.0f;
        const float* zr = zs + tid * ZSTRIDE;
        #pragma unroll 8
        for (int c = 0; c < DIM; c++)
            s = __fadd_rn(s, __fmul_rn(zr[c], zr[c]));
        zn[tid] = s;
    }

    int zrow[8], wrow[8];
    #pragma unroll
    for (int i = 0; i < 8; i++) zrow[i] = (tg + 8 * i) * ZSTRIDE;
    #pragma unroll
    for (int j = 0; j < 8; j++) wrow[j] = (cg + 32 * j) * ZSTRIDE;

    float bestv[8];
    int   besti[8];
    #pragma unroll
    for (int i = 0; i < 8; i++) { bestv[i] = CUDART_INF_F; besti[i] = 0; }

    float znr[8];
    bool znr_loaded = false;

    for (int chunk = 0; chunk < N_CHUNKS; chunk++) {
        const int cb = chunk * CODES_PER_CHUNK;
        __syncthreads();   // previous chunk fully consumed before overwriting ws/en

        // load 256-code chunk (float4, coalesced; codebook is L2-resident)
        for (int f = tid; f < CODES_PER_CHUNK * (DIM / 4); f += 256) {
            int code = f >> 5;       // 32 float4 per row
            int d4   = f & 31;
            float4 v = ((const float4*)(w + (size_t)(cb + code) * DIM))[d4];
            *(float4*)&ws[code * ZSTRIDE + d4 * 4] = v;
        }
        if (tid < CODES_PER_CHUNK) en[tid] = g_enorm[cb + tid];
        __syncthreads();

        if (!znr_loaded) {  // cache znorm in regs once (zn valid after first sync pair)
            #pragma unroll
            for (int i = 0; i < 8; i++) znr[i] = zn[tg + 8 * i];
            znr_loaded = true;
        }

        // ---- 8 tokens x 8 codes register tile, packed f32x2 along d ----
        unsigned long long acc[8][8];
        #pragma unroll
        for (int i = 0; i < 8; i++)
            #pragma unroll
            for (int j = 0; j < 8; j++) acc[i][j] = 0ull;

        #pragma unroll 2
        for (int d4 = 0; d4 < DIM / 4; d4++) {
            unsigned long long za0[8], za1[8];
            #pragma unroll
            for (int i = 0; i < 8; i++) {
                ulonglong2 v = *(const ulonglong2*)(zs + zrow[i] + d4 * 4);
                za0[i] = v.x; za1[i] = v.y;
            }
            #pragma unroll
            for (int j = 0; j < 8; j++) {
                ulonglong2 wv = *(const ulonglong2*)(ws + wrow[j] + d4 * 4);
                #pragma unroll
                for (int i = 0; i < 8; i++) {
                    acc[i][j] = ffma2(za0[i], wv.x, acc[i][j]);
                    acc[i][j] = ffma2(za1[i], wv.y, acc[i][j]);
                }
            }
        }

        // ---- fused distance + running argmin (exact reference rounding) ----
        #pragma unroll
        for (int j = 0; j < 8; j++) {
            const int code = cb + cg + 32 * j;
            const float ec = en[cg + 32 * j];
            #pragma unroll
            for (int i = 0; i < 8; i++) {
                float lo, hi;
                unpack2(acc[i][j], lo, hi);
                float dot = lo + hi;
                float s   = znr[i] + ec;          // (znorm + enorm), rounded
                float dis = fmaf(-2.0f, dot, s);  // == fl(s - 2*dot)
                if (dis < bestv[i]) { bestv[i] = dis; besti[i] = code; }
            }
        }
    }

    // ---- cross-thread argmin reduce (first-index tie-break) ----
    __syncthreads();
    #pragma unroll
    for (int i = 0; i < 8; i++) {
        int t = tg + 8 * i;
        rv[t * 32 + cg] = bestv[i];
        ri[t * 32 + cg] = besti[i];
    }
    __syncthreads();
    if (tid < TOK_PER_BLK) {
        float bv = rv[tid * 32];
        int   bi = ri[tid * 32];
        for (int c2 = 1; c2 < 32; c2++) {
            float v = rv[tid * 32 + c2];
            int   ii = ri[tid * 32 + c2];
            if (v < bv || (v == bv && ii < bi)) { bv = v; bi = ii; }
        }
        inds[tid] = bi;
    }
    __syncthreads();

    // ---- gather + straight-through output + loss partials ----
    double s1 = 0.0, s3 = 0.0;
    float* obase = out + (size_t)b * (128 * 4096) + hw0;
    for (int idx = tid; idx < TOK_PER_BLK * DIM; idx += 256) {
        int c = idx >> 6;
        int t = idx & 63;
        float z  = zs[t * ZSTRIDE + c];
        float q  = __ldg(&w[(size_t)inds[t] * DIM + c]);
        float dq = q - z;            // fl(z_q - z)
        float ov = z + dq;           // out = z + stop_grad(z_q - z)
        float d3 = z - ov;           // batch - out
        obase[(size_t)c * 4096 + t] = ov;
        float sq1 = dq * dq;         // squared in fp32 like the reference
        float sq3 = d3 * d3;
        s1 += (double)sq1;
        s3 += (double)sq3;
    }

    // block-reduce doubles (reuse ws; 8-byte aligned region)
    __syncthreads();
    double* red = (double*)ws;
    red[tid]       = s1;
    red[256 + tid] = s3;
    __syncthreads();
    #pragma unroll
    for (int stride = 128; stride > 0; stride >>= 1) {
        if (tid < stride) {
            red[tid]       += red[tid + stride];
            red[256 + tid] += red[256 + tid + stride];
        }
        __syncthreads();
    }
    if (tid == 0) {
        atomicAdd(&g_s1, red[0]);
        atomicAdd(&g_s3, red[256]);
    }
}

// ---------------- finalize: loss scalar ----------------
__global__ void vq_finalize(float* __restrict__ out, int out_size) {
    if (out_size <= TOT_ELEMS) return;
    const double inv = 1.0 / (double)TOT_ELEMS;
    float t1 = (float)(g_s1 * inv);       // mean((z_q - z)^2)  == term1 == term2
    float t3 = (float)(g_s3 * inv);       // mean((batch - out)^2)
    out[TOT_ELEMS] = (t1 + t1) + t3 * 50.0f;
}

// ---------------- launch ----------------
extern "C" void kernel_launch(void* const* d_in, const int* in_sizes, int n_in,
                              void* d_out, int out_size) {
    const float* batch = (const float*)d_in[0];
    const float* wq    = (const float*)d_in[1];
    if (n_in >= 2 && in_sizes[0] == NUM_CODES * DIM) {  // defensive: swapped order
        const float* t = batch; batch = wq; wq = t;
    }
    float* out = (float*)d_out;

    const int SMEM_BYTES =
        (TOK_PER_BLK * ZSTRIDE + CODES_PER_CHUNK * ZSTRIDE +
         TOK_PER_BLK + CODES_PER_CHUNK + TOK_PER_BLK) * (int)sizeof(float);

    cudaFuncSetAttribute(vq_main, cudaFuncAttributeMaxDynamicSharedMemorySize,
                         SMEM_BYTES);

    vq_prep<<<(NUM_CODES * 32 + 255) / 256, 256>>>(wq);
    vq_main<<<N_TOKENS / TOK_PER_BLK, 256, SMEM_BYTES>>>(batch, wq, out);
    vq_finalize<<<1, 1>>>(out, out_size);
}

// round 6
// speedup vs baseline: 1.6060x; 1.6060x over previous
#include <cuda_runtime.h>
#include <cuda_bf16.h>
#include <math_constants.h>

#define NUM_CODES 2560
#define DIM       128
#define N_TOKENS  65536
#define TOT_ELEMS 8388608
#define TPC       256          // tokens per CTA (tensor pass)
#define CPC       64           // codes per chunk (tensor pass)
#define N_CHUNKS  40
#define NSTAGE    3
#define THRESH    1e-4f        // gap threshold: > 2*tensor-err-bound + ulp(256)

#define RS          272                    // padded row stride bytes (136 bf16)
#define HALF_STAGE  (64 * RS)
#define STAGE_BYTES (64 * RS * 2)
#define OFF_BST     0                      // B stages / A-hi temp
#define OFF_ALO     (NSTAGE * STAGE_BYTES) // 104448
#define OFF_EN      (OFF_ALO + 256 * RS)   // 174080
#define OFF_ZN      (OFF_EN + NUM_CODES * 4)
#define SMEM_TENSOR (OFF_ZN + 1024)

// recheck (R1-core) smem layout, in floats
#define ZSTR        132
#define RT          16                     // tokens per recheck CTA
#define R_CHUNK     256
#define R_NCH       10

__device__ __align__(16) float         g_enorm[NUM_CODES];
__device__ __align__(16) __nv_bfloat16 g_whi[NUM_CODES * DIM];
__device__ __align__(16) __nv_bfloat16 g_wlo[NUM_CODES * DIM];
__device__ int    g_inds[N_TOKENS];
__device__ int    g_list[N_TOKENS];
__device__ int    g_nflag;
__device__ double g_s1, g_s3;

// ---------- helpers ----------
__device__ __forceinline__ unsigned smem_u32(const void* p) {
    unsigned a;
    asm("{ .reg .u64 t; cvta.to.shared.u64 t, %1; cvt.u32.u64 %0, t; }" : "=r"(a) : "l"(p));
    return a;
}
__device__ __forceinline__ unsigned lds32(unsigned a) {
    unsigned v;
    asm volatile("ld.shared.b32 %0, [%1];" : "=r"(v) : "r"(a));
    return v;
}
__device__ __forceinline__ float2 lds64f(unsigned a) {
    float2 v;
    asm volatile("ld.shared.v2.f32 {%0, %1}, [%2];" : "=f"(v.x), "=f"(v.y) : "r"(a));
    return v;
}
__device__ __forceinline__ void mma_bf16(float* c, const unsigned* a,
                                         unsigned b0, unsigned b1) {
    asm volatile(
        "mma.sync.aligned.m16n8k16.row.col.f32.bf16.bf16.f32 "
        "{%0,%1,%2,%3}, {%4,%5,%6,%7}, {%8,%9}, {%0,%1,%2,%3};"
        : "+f"(c[0]), "+f"(c[1]), "+f"(c[2]), "+f"(c[3])
        : "r"(a[0]), "r"(a[1]), "r"(a[2]), "r"(a[3]), "r"(b0), "r"(b1));
}
__device__ __forceinline__ unsigned long long ffma2(unsigned long long a,
                                                    unsigned long long b,
                                                    unsigned long long c) {
    unsigned long long d;
    asm("fma.rn.f32x2 %0, %1, %2, %3;" : "=l"(d) : "l"(a), "l"(b), "l"(c));
    return d;
}
__device__ __forceinline__ void unpack2(unsigned long long p, float& lo, float& hi) {
    asm("mov.b64 {%0, %1}, %2;" : "=f"(lo), "=f"(hi) : "l"(p));
}

// ---------- prep ----------
__global__ void vq_prep(const float* __restrict__ w) {
    int gtid = blockIdx.x * blockDim.x + threadIdx.x;
    if (gtid == 0) { g_s1 = 0.0; g_s3 = 0.0; g_nflag = 0; }
    int gw = gtid >> 5, lane = threadIdx.x & 31;
    if (gw < NUM_CODES) {
        const float* row = w + (size_t)gw * DIM;
        float s = 0.0f;
        #pragma unroll
        for (int k = lane; k < DIM; k += 32) {
            float v = row[k];
            s = __fadd_rn(s, __fmul_rn(v, v));
        }
        #pragma unroll
        for (int off = 16; off > 0; off >>= 1) s += __shfl_xor_sync(~0u, s, off);
        if (lane == 0) g_enorm[gw] = s;
    }
    int stride = gridDim.x * blockDim.x;
    for (int i = gtid; i < NUM_CODES * DIM; i += stride) {
        float v = w[i];
        __nv_bfloat16 h = __float2bfloat16(v);
        g_whi[i] = h;
        g_wlo[i] = __float2bfloat16(v - __bfloat162float(h));
    }
}

// ---------- tensor pass ----------
__device__ __forceinline__ void issue_chunk(unsigned sb, int tid, int cn, int st) {
    const uint4* gh = ((const uint4*)g_whi) + (size_t)cn * 1024;
    const uint4* gl = ((const uint4*)g_wlo) + (size_t)cn * 1024;
    unsigned base = sb + OFF_BST + st * STAGE_BYTES;
    #pragma unroll
    for (int i = 0; i < 4; i++) {
        int f = tid + i * 256;
        unsigned d = base + (f >> 4) * RS + (f & 15) * 16;
        asm volatile("cp.async.cg.shared.global [%0], [%1], 16;" :: "r"(d), "l"(gh + f));
        asm volatile("cp.async.cg.shared.global [%0], [%1], 16;" :: "r"(d + HALF_STAGE), "l"(gl + f));
    }
}

__global__ void __launch_bounds__(256, 1)
vq_tensor(const float* __restrict__ batch) {
    extern __shared__ char smem[];
    const unsigned sb = smem_u32(smem);
    float* zn_s = (float*)(smem + OFF_ZN);

    const int tid = threadIdx.x, wid = tid >> 5, lane = tid & 31;
    const int n0 = blockIdx.x * TPC, b = n0 >> 12, hw0 = n0 & 4095;
    const float* zbase = batch + (size_t)b * (DIM * 4096) + hw0;

    // prologue: thread tid = token tid: znorm (R1 order) + bf16 hi/lo split
    {
        const float* zp = zbase + tid;
        float acc = 0.0f;
        #pragma unroll 4
        for (int c = 0; c < DIM; c += 2) {
            float z0 = zp[(size_t)c * 4096];
            float z1 = zp[(size_t)(c + 1) * 4096];
            acc = __fadd_rn(acc, __fmul_rn(z0, z0));
            acc = __fadd_rn(acc, __fmul_rn(z1, z1));
            __nv_bfloat16 h0 = __float2bfloat16(z0), h1 = __float2bfloat16(z1);
            __nv_bfloat16 l0 = __float2bfloat16(z0 - __bfloat162float(h0));
            __nv_bfloat16 l1 = __float2bfloat16(z1 - __bfloat162float(h1));
            unsigned hp = (unsigned)__bfloat16_as_ushort(h0) |
                          ((unsigned)__bfloat16_as_ushort(h1) << 16);
            unsigned lp = (unsigned)__bfloat16_as_ushort(l0) |
                          ((unsigned)__bfloat16_as_ushort(l1) << 16);
            *(unsigned*)(smem + OFF_BST + tid * RS + c * 2) = hp;
            *(unsigned*)(smem + OFF_ALO + tid * RS + c * 2) = lp;
        }
        zn_s[tid] = acc;
    }
    for (int i = tid; i < NUM_CODES; i += 256)
        ((float*)(smem + OFF_EN))[i] = g_enorm[i];
    __syncthreads();

    // chunk-invariant A-hi fragments -> registers
    const unsigned Rb = wid * 32 + (lane >> 2);
    const unsigned Cb = (lane & 3) * 2;
    unsigned Ah[2][8][4];
    #pragma unroll
    for (int mt = 0; mt < 2; mt++)
        #pragma unroll
        for (int ks = 0; ks < 8; ks++) {
            unsigned a = sb + OFF_BST + (Rb + mt * 16) * RS + (ks * 16 + Cb) * 2;
            Ah[mt][ks][0] = lds32(a);
            Ah[mt][ks][1] = lds32(a + 8 * RS);
            Ah[mt][ks][2] = lds32(a + 16);
            Ah[mt][ks][3] = lds32(a + 8 * RS + 16);
        }
    float znr[4];
    #pragma unroll
    for (int j = 0; j < 4; j++) znr[j] = zn_s[Rb + j * 8];
    __syncthreads();

    issue_chunk(sb, tid, 0, 0);
    asm volatile("cp.async.commit_group;" ::: "memory");
    issue_chunk(sb, tid, 1, 1);
    asm volatile("cp.async.commit_group;" ::: "memory");
    issue_chunk(sb, tid, 2, 2);
    asm volatile("cp.async.commit_group;" ::: "memory");

    float acc[2][8][4];
    #pragma unroll
    for (int mt = 0; mt < 2; mt++)
        #pragma unroll
        for (int nt = 0; nt < 8; nt++)
            #pragma unroll
            for (int q = 0; q < 4; q++) acc[mt][nt][q] = 0.0f;
    float bv1[4] = {CUDART_INF_F, CUDART_INF_F, CUDART_INF_F, CUDART_INF_F};
    float bv2[4] = {CUDART_INF_F, CUDART_INF_F, CUDART_INF_F, CUDART_INF_F};
    int   bi1[4] = {0, 0, 0, 0};

    const unsigned bfrag_base = sb + OFF_BST + (lane >> 2) * RS + Cb * 2;
    const unsigned alo_base   = sb + OFF_ALO + Rb * RS + Cb * 2;

    for (int cn = 0; cn < N_CHUNKS; cn++) {
        asm volatile("cp.async.wait_group 2;" ::: "memory");
        __syncthreads();
        const unsigned sbase = (unsigned)(cn % NSTAGE) * STAGE_BYTES;

        #pragma unroll
        for (int ks = 0; ks < 8; ks++) {
            unsigned al[2][4];
            #pragma unroll
            for (int mt = 0; mt < 2; mt++) {
                unsigned a = alo_base + mt * 16 * RS + ks * 32;
                al[mt][0] = lds32(a);
                al[mt][1] = lds32(a + 8 * RS);
                al[mt][2] = lds32(a + 16);
                al[mt][3] = lds32(a + 8 * RS + 16);
            }
            #pragma unroll
            for (int nt = 0; nt < 8; nt++) {
                unsigned ba  = bfrag_base + sbase + nt * 8 * RS + ks * 32;
                unsigned bh0 = lds32(ba),              bh1 = lds32(ba + 16);
                unsigned bl0 = lds32(ba + HALF_STAGE), bl1 = lds32(ba + HALF_STAGE + 16);
                #pragma unroll
                for (int mt = 0; mt < 2; mt++) {
                    mma_bf16(acc[mt][nt], Ah[mt][ks], bh0, bh1);
                    mma_bf16(acc[mt][nt], al[mt],     bh0, bh1);
                    mma_bf16(acc[mt][nt], Ah[mt][ks], bl0, bl1);
                }
            }
        }
        __syncthreads();
        if (cn + NSTAGE < N_CHUNKS) issue_chunk(sb, tid, cn + NSTAGE, cn % NSTAGE);
        asm volatile("cp.async.commit_group;" ::: "memory");

        // fused distance + best/second-best tracking; reset acc
        #pragma unroll
        for (int nt = 0; nt < 8; nt++) {
            const int code0 = cn * CPC + nt * 8 + (int)Cb;
            float2 e = lds64f(sb + OFF_EN + (unsigned)code0 * 4);
            #pragma unroll
            for (int mt = 0; mt < 2; mt++) {
                float d0 = fmaf(-2.0f, acc[mt][nt][0], znr[2 * mt] + e.x);
                float d1 = fmaf(-2.0f, acc[mt][nt][1], znr[2 * mt] + e.y);
                float d2 = fmaf(-2.0f, acc[mt][nt][2], znr[2 * mt + 1] + e.x);
                float d3 = fmaf(-2.0f, acc[mt][nt][3], znr[2 * mt + 1] + e.y);
                int x = 2 * mt, y = 2 * mt + 1;
                if (d0 < bv1[x]) { bv2[x] = bv1[x]; bv1[x] = d0; bi1[x] = code0; }
                else if (d0 < bv2[x]) bv2[x] = d0;
                if (d1 < bv1[x]) { bv2[x] = bv1[x]; bv1[x] = d1; bi1[x] = code0 + 1; }
                else if (d1 < bv2[x]) bv2[x] = d1;
                if (d2 < bv1[y]) { bv2[y] = bv1[y]; bv1[y] = d2; bi1[y] = code0; }
                else if (d2 < bv2[y]) bv2[y] = d2;
                if (d3 < bv1[y]) { bv2[y] = bv1[y]; bv1[y] = d3; bi1[y] = code0 + 1; }
                else if (d3 < bv2[y]) bv2[y] = d3;
                acc[mt][nt][0] = 0.0f; acc[mt][nt][1] = 0.0f;
                acc[mt][nt][2] = 0.0f; acc[mt][nt][3] = 0.0f;
            }
        }
    }

    // quad merge of (best, second-best); flag near-ties for exact recheck
    #pragma unroll
    for (int j = 0; j < 4; j++) {
        float v1 = bv1[j], v2 = bv2[j];
        int   i1 = bi1[j];
        #pragma unroll
        for (int off = 1; off <= 2; off <<= 1) {
            float o1  = __shfl_xor_sync(~0u, v1, off);
            int   o1i = __shfl_xor_sync(~0u, i1, off);
            float o2  = __shfl_xor_sync(~0u, v2, off);
            if (o1 < v1 || (o1 == v1 && o1i < i1)) {
                v2 = fminf(v1, o2); v1 = o1; i1 = o1i;
            } else {
                v2 = fminf(v2, o1);
            }
        }
        if ((lane & 3) == 0) {
            int token = n0 + (int)Rb + j * 8;
            g_inds[token] = i1;
            if (v2 - v1 < THRESH) {
                int p = atomicAdd(&g_nflag, 1);
                g_list[p] = token;
            }
        }
    }
}

// ---------- recheck: verbatim Round-1 numerics for flagged tokens ----------
__global__ void __launch_bounds__(256, 1)
vq_recheck(const float* __restrict__ batch, const float* __restrict__ w) {
    const int base = blockIdx.x * RT;
    const int nf = *(volatile int*)&g_nflag;
    if (base >= nf) return;

    extern __shared__ float sm[];
    float* zs = sm;                               // 16*132
    float* ws = sm + RT * ZSTR;                   // 256*132
    float* zn = ws + R_CHUNK * ZSTR;              // 16
    float* en = zn + RT;                          // 256
    int*   tk = (int*)(en + R_CHUNK);             // 16
    int*   tb = tk + RT;                          // 16 (precomputed base offsets)
    float* rv = ws;                               // reduce alias
    int*   ri = (int*)(ws + 512);

    const int tid = threadIdx.x;
    if (tid < RT) {
        int t = (base + tid < nf) ? g_list[base + tid] : -1;
        tk[tid] = t;
        int tt = (t >= 0) ? t : 0;
        tb[tid] = (tt >> 12) * (DIM * 4096) + (tt & 4095);
    }
    __syncthreads();

    for (int idx = tid; idx < RT * DIM; idx += 256) {
        int t = idx & 15, c = idx >> 4;
        zs[t * ZSTR + c] = batch[(size_t)tb[t] + (size_t)c * 4096];
    }
    __syncthreads();

    if (tid < RT) {                               // znorm, R1 order
        float s = 0.0f;
        const float* zr = zs + tid * ZSTR;
        #pragma unroll 8
        for (int c = 0; c < DIM; c++)
            s = __fadd_rn(s, __fmul_rn(zr[c], zr[c]));
        zn[tid] = s;
    }
    __syncthreads();

    const int tg = tid & 7;          // tokens tg, tg+8
    const int cg = tid >> 3;         // codes cg + 32j

    int zrow[2], wrow[8];
    zrow[0] = tg * ZSTR; zrow[1] = (tg + 8) * ZSTR;
    #pragma unroll
    for (int j = 0; j < 8; j++) wrow[j] = (cg + 32 * j) * ZSTR;
    float znrv[2] = {zn[tg], zn[tg + 8]};

    float bestv[2] = {CUDART_INF_F, CUDART_INF_F};
    int   besti[2] = {0, 0};

    for (int chunk = 0; chunk < R_NCH; chunk++) {
        const int cb = chunk * R_CHUNK;
        __syncthreads();
        for (int f = tid; f < R_CHUNK * 32; f += 256) {
            int code = f >> 5, d4 = f & 31;
            float4 v = ((const float4*)(w + (size_t)(cb + code) * DIM))[d4];
            *(float4*)&ws[code * ZSTR + d4 * 4] = v;
        }
        if (tid < R_CHUNK) en[tid] = g_enorm[cb + tid];
        __syncthreads();

        unsigned long long acc[2][8];
        #pragma unroll
        for (int i = 0; i < 2; i++)
            #pragma unroll
            for (int j = 0; j < 8; j++) acc[i][j] = 0ull;

        #pragma unroll 2
        for (int d4 = 0; d4 < DIM / 4; d4++) {
            unsigned long long za0[2], za1[2];
            #pragma unroll
            for (int i = 0; i < 2; i++) {
                ulonglong2 v = *(const ulonglong2*)(zs + zrow[i] + d4 * 4);
                za0[i] = v.x; za1[i] = v.y;
            }
            #pragma unroll
            for (int j = 0; j < 8; j++) {
                ulonglong2 wv = *(const ulonglong2*)(ws + wrow[j] + d4 * 4);
                #pragma unroll
                for (int i = 0; i < 2; i++) {
                    acc[i][j] = ffma2(za0[i], wv.x, acc[i][j]);
                    acc[i][j] = ffma2(za1[i], wv.y, acc[i][j]);
                }
            }
        }
        #pragma unroll
        for (int j = 0; j < 8; j++) {
            const int code = cb + cg + 32 * j;
            const float ec = en[cg + 32 * j];
            #pragma unroll
            for (int i = 0; i < 2; i++) {
                float lo, hi;
                unpack2(acc[i][j], lo, hi);
                float dot = lo + hi;
                float s   = znrv[i] + ec;
                float dis = fmaf(-2.0f, dot, s);
                if (dis < bestv[i]) { bestv[i] = dis; besti[i] = code; }
            }
        }
    }

    __syncthreads();
    #pragma unroll
    for (int i = 0; i < 2; i++) {
        int t = tg + 8 * i;
        rv[t * 32 + cg] = bestv[i];
        ri[t * 32 + cg] = besti[i];
    }
    __syncthreads();
    if (tid < RT) {
        float bvv = rv[tid * 32];
        int   bii = ri[tid * 32];
        for (int c2 = 1; c2 < 32; c2++) {
            float v = rv[tid * 32 + c2];
            int  ii = ri[tid * 32 + c2];
            if (v < bvv || (v == bvv && ii < bii)) { bvv = v; bii = ii; }
        }
        if (tk[tid] >= 0) g_inds[tk[tid]] = bii;
    }
}

// ---------- output + loss ----------
__global__ void __launch_bounds__(256, 1)
vq_output(const float* __restrict__ batch, const float* __restrict__ w,
          float* __restrict__ out) {
    __shared__ double red[512];
    const int tid = threadIdx.x;
    const int token = blockIdx.x * 256 + tid;
    const int b = token >> 12, hw = token & 4095;
    const size_t baseo = (size_t)b * (DIM * 4096) + hw;
    const int ind = g_inds[token];

    double s1 = 0.0, s3 = 0.0;
    for (int c = 0; c < DIM; c++) {
        float z = batch[baseo + (size_t)c * 4096];
        float q = __ldg(&w[(size_t)ind * DIM + c]);
        float dq = q - z;
        float ov = z + dq;
        float d3 = z - ov;
        out[baseo + (size_t)c * 4096] = ov;
        s1 += (double)(dq * dq);
        s3 += (double)(d3 * d3);
    }
    red[tid] = s1; red[256 + tid] = s3;
    __syncthreads();
    #pragma unroll
    for (int st = 128; st > 0; st >>= 1) {
        if (tid < st) { red[tid] += red[tid + st]; red[256 + tid] += red[256 + tid + st]; }
        __syncthreads();
    }
    if (tid == 0) { atomicAdd(&g_s1, red[0]); atomicAdd(&g_s3, red[256]); }
}

// ---------- finalize ----------
__global__ void vq_finalize(float* __restrict__ out, int out_size) {
    if (out_size <= TOT_ELEMS) return;
    const double inv = 1.0 / (double)TOT_ELEMS;
    float t1 = (float)(g_s1 * inv);
    float t3 = (float)(g_s3 * inv);
    out[TOT_ELEMS] = (t1 + t1) + t3 * 50.0f;
}

// ---------- launch ----------
extern "C" void kernel_launch(void* const* d_in, const int* in_sizes, int n_in,
                              void* d_out, int out_size) {
    const float* batch = (const float*)d_in[0];
    const float* wq    = (const float*)d_in[1];
    if (n_in >= 2 && in_sizes[0] == NUM_CODES * DIM) {
        const float* t = batch; batch = wq; wq = t;
    }
    float* out = (float*)d_out;

    const int SMEM_RECHECK = (RT * ZSTR + R_CHUNK * ZSTR + RT + R_CHUNK) * 4 + 128;

    cudaFuncSetAttribute(vq_tensor, cudaFuncAttributeMaxDynamicSharedMemorySize,
                         SMEM_TENSOR);
    cudaFuncSetAttribute(vq_recheck, cudaFuncAttributeMaxDynamicSharedMemorySize,
                         SMEM_RECHECK);

    vq_prep<<<320, 256>>>(wq);
    vq_tensor<<<N_TOKENS / TPC, 256, SMEM_TENSOR>>>(batch);
    vq_recheck<<<N_TOKENS / RT, 256, SMEM_RECHECK>>>(batch, wq);
    vq_output<<<N_TOKENS / 256, 256>>>(batch, wq, out);
    vq_finalize<<<1, 1>>>(out, out_size);
}